// round 16
// baseline (speedup 1.0000x reference)
#include <cuda_runtime.h>
#include <cstdint>

#define BN 8192
#define CN 8192
#define DK 256
#define KC 16
#define NCH (DK / KC)             // 16 chunks (8 pairs)
#define LDRB 96                   // smem row stride bytes (64 B data + 32 pad)
#define TILE_B (128 * LDRB)       // 12288 B per 128-row array tile
#define STAGE_B (2 * TILE_B)      // A + B = 24576 B
#define NSTAGE 4
#define LDT 132                   // transpose smem stride (floats)
#define NTRI 2080                 // 64*65/2 triangular tiles
#define SMEM_BYTES (NSTAGE * STAGE_B)   // 98304

typedef unsigned long long ull;

// ---------------- scratch ----------------------------------------------------
__device__ float g_sqx[BN];
__device__ float g_sqc[CN];
__device__ float g_colsum[CN];
__device__ unsigned g_rowmin_bits[BN];
__device__ ull g_rowpack[CN];
__device__ float g_dpos[BN];
__device__ int g_lab32;

// chunk-major k-pair-interleaved fp32: [chunk][row][16]
__device__ float g_xi[NCH * BN * KC];
__device__ float g_ci[NCH * CN * KC];

__device__ __forceinline__ uint32_t s2u(const void* p) {
    uint32_t a;
    asm("{ .reg .u64 t; cvta.to.shared.u64 t, %1; cvt.u32.u64 %0, t; }" : "=r"(a) : "l"(p));
    return a;
}
__device__ __forceinline__ void cp16(uint32_t dst, const void* src) {
    asm volatile("cp.async.cg.shared.global [%0], [%1], 16;" :: "r"(dst), "l"(src));
}
// streaming (evict-first) store of a float2 — keeps A/B tiles resident in L2
__device__ __forceinline__ void stcs2(float* addr, float d0, float d1) {
    asm volatile("st.global.cs.v2.f32 [%0], {%1, %2};" :: "l"(addr), "f"(d0), "f"(d1)
                 : "memory");
}
#define LDS64(r0, r1, addr)                                                     \
    asm volatile("ld.shared.v2.b32 {%0,%1}, [%2];" : "=r"(r0), "=r"(r1) : "r"(addr))
#define MMA_TF32(d, a, b)                                                       \
    asm volatile(                                                               \
        "mma.sync.aligned.m16n8k8.row.col.f32.tf32.tf32.f32 "                   \
        "{%0,%1,%2,%3}, {%4,%5,%6,%7}, {%8,%9}, {%0,%1,%2,%3};"                 \
        : "+f"((d)[0]), "+f"((d)[1]), "+f"((d)[2]), "+f"((d)[3])                \
        : "r"((a)[0]), "r"((a)[1]), "r"((a)[2]), "r"((a)[3]),                   \
          "r"((b)[0]), "r"((b)[1]))

// ---------------- fused prep ---------------------------------------------------
__global__ void prep_all(const float* __restrict__ x,
                         const float* __restrict__ centers,
                         const unsigned* __restrict__ lw) {
    int bid = blockIdx.x;
    if (bid >= 2048) {
        int i = (bid - 2048) * 256 + threadIdx.x;
        g_colsum[i] = 0.0f;
        g_rowmin_bits[i] = 0x7F7FFFFFu;
        g_rowpack[i] = 0xFFFFFFFFFFFFFFFFull;
        if (i == 0) g_lab32 = 0;
        if (i < BN / 2) {
            if (lw[2 * i + 1] != 0u) g_lab32 = 1;
        }
        return;
    }
    int which = bid >> 10;
    const float* X = which ? centers : x;
    int warp = ((bid & 1023) * 256 + (int)threadIdx.x) >> 5;
    int lane = threadIdx.x & 31;
    const float4* p = reinterpret_cast<const float4*>(X + (size_t)warp * DK);
    float4 v0 = p[lane * 2], v1 = p[lane * 2 + 1];
    float v[8] = {v0.x, v0.y, v0.z, v0.w, v1.x, v1.y, v1.z, v1.w};
    float s = 0.0f;
#pragma unroll
    for (int i = 0; i < 8; i++) s += v[i] * v[i];
    int ch = lane >> 1, ks = lane & 1;
    float* dst = (which ? g_ci : g_xi) + ((size_t)ch * BN + warp) * 16 + ks * 8;
    *(float4*)dst = make_float4(v[0], v[4], v[1], v[5]);
    *(float4*)(dst + 4) = make_float4(v[2], v[6], v[3], v[7]);
#pragma unroll
    for (int o = 16; o; o >>= 1) s += __shfl_xor_sync(0xffffffffu, s, o);
    if (lane == 0) { if (which) g_sqc[warp] = s; else g_sqx[warp] = s; }
}

// ---------------- GEMM body: 256 threads, 2m x 4n warps, warp tile 64x32 ------
template <int MODE>
__device__ __forceinline__ void gemm_body(
    const void* __restrict__ labels, float* __restrict__ out3,
    char* smem, int bx, int by)
{
    const uint32_t sm0 = s2u(smem);
    const int tid = threadIdx.x;
    const int wid = tid >> 5;
    const int lane = tid & 31;
    const int g = lane >> 2;
    const int t = lane & 3;
    const int warp_m = wid >> 2;
    const int warp_n = wid & 3;
    const int mrow0 = by * 128;
    const int ncol0 = bx * 128;
    const bool diag = (MODE == 2) && (bx == by);

    const char* pA = (const char*)(MODE == 1 ? g_xi : g_ci);
    const char* pB = (const char*)g_ci;
    const int r_ld = tid >> 2;
    const int q_ld = tid & 3;
    const uint32_t dstO = r_ld * LDRB + q_ld * 16;

#define ISSUE_PAIR(pp)                                                         \
    {                                                                          \
        _Pragma("unroll")                                                      \
        for (int cc2 = 0; cc2 < 2; cc2++) {                                    \
            const int c_ = (pp) * 2 + cc2;                                     \
            const uint32_t sb_ = sm0 + (c_ & (NSTAGE - 1)) * STAGE_B;          \
            _Pragma("unroll")                                                  \
            for (int it = 0; it < 2; it++) {                                   \
                const size_t ga = ((size_t)(c_ * BN + mrow0 + r_ld + it * 64)) * 64 + q_ld * 16; \
                const size_t gb = ((size_t)(c_ * CN + ncol0 + r_ld + it * 64)) * 64 + q_ld * 16; \
                cp16(sb_ + dstO + it * 64 * LDRB, pA + ga);                    \
                cp16(sb_ + TILE_B + dstO + it * 64 * LDRB, pB + gb);           \
            }                                                                  \
        }                                                                      \
        asm volatile("cp.async.commit_group;");                                \
    }

    float acc[4][4][4];
#pragma unroll
    for (int i = 0; i < 4; i++)
#pragma unroll
        for (int j = 0; j < 4; j++)
#pragma unroll
            for (int u = 0; u < 4; u++) acc[i][j][u] = 0.0f;

    ISSUE_PAIR(0);

    const uint32_t aAddr0 = (warp_m * 64 + g) * LDRB + t * 8;
    const uint32_t bAddr0 = TILE_B + (warp_n * 32 + g) * LDRB + t * 8;

    for (int p = 0; p < NCH / 2; p++) {
        asm volatile("cp.async.wait_group 0;");
        __syncthreads();
        if (p + 1 < NCH / 2) ISSUE_PAIR(p + 1);

#pragma unroll
        for (int cc = 0; cc < 2; cc++) {
            const int c = 2 * p + cc;
            const uint32_t sb = sm0 + (c & (NSTAGE - 1)) * STAGE_B;
            // merged fragment load: BOTH k8 sub-steps up front (one stall window)
            uint32_t af[2][4][4], bf[2][4][2];
#pragma unroll
            for (int ks = 0; ks < 2; ks++) {
                const uint32_t ko = ks * 32;
#pragma unroll
                for (int mt = 0; mt < 4; mt++) {
                    uint32_t base = sb + aAddr0 + ko + mt * (16 * LDRB);
                    LDS64(af[ks][mt][0], af[ks][mt][2], base);
                    LDS64(af[ks][mt][1], af[ks][mt][3], base + 8 * LDRB);
                }
#pragma unroll
                for (int nt = 0; nt < 4; nt++)
                    LDS64(bf[ks][nt][0], bf[ks][nt][1], sb + bAddr0 + ko + nt * (8 * LDRB));
            }
#pragma unroll
            for (int ks = 0; ks < 2; ks++)
#pragma unroll
                for (int mt = 0; mt < 4; mt++)
#pragma unroll
                    for (int nt = 0; nt < 4; nt++)
                        MMA_TF32(acc[mt][nt], af[ks][mt], bf[ks][nt]);
        }
    }
    __syncthreads();   // pipeline smem free for reuse

    // ---------------- epilogue ----------------
    const float* sqa = (MODE == 1) ? (const float*)g_sqx : (const float*)g_sqc;
    float sarow[8];
    int lbl[8];
#pragma unroll
    for (int mt = 0; mt < 4; mt++)
#pragma unroll
        for (int h = 0; h < 2; h++) {
            int r = mrow0 + warp_m * 64 + mt * 16 + h * 8 + g;
            sarow[mt * 2 + h] = sqa[r];
            if (MODE == 1)
                lbl[mt * 2 + h] = g_lab32 ? ((const int*)labels)[r]
                                          : (int)((const long long*)labels)[r];
        }
    float sbcol[8];
#pragma unroll
    for (int nt = 0; nt < 4; nt++) {
        int c0 = ncol0 + warp_n * 32 + nt * 8 + t * 2;
        sbcol[nt * 2] = g_sqc[c0];
        sbcol[nt * 2 + 1] = g_sqc[c0 + 1];
    }

    if (MODE == 1) {
        float minv[8];
#pragma unroll
        for (int i = 0; i < 8; i++) minv[i] = 3.0e38f;
#pragma unroll
        for (int mt = 0; mt < 4; mt++)
#pragma unroll
            for (int h = 0; h < 2; h++) {
                const int ri = mt * 2 + h;
                const int r = mrow0 + warp_m * 64 + mt * 16 + h * 8 + g;
                const float sa = sarow[ri];
#pragma unroll
                for (int nt = 0; nt < 4; nt++) {
                    const int c0 = ncol0 + warp_n * 32 + nt * 8 + t * 2;
                    float d0 = fminf(fmaxf(fmaf(-2.0f, acc[mt][nt][h * 2], sa + sbcol[nt * 2]), 1e-12f), 1e12f);
                    float d1 = fminf(fmaxf(fmaf(-2.0f, acc[mt][nt][h * 2 + 1], sa + sbcol[nt * 2 + 1]), 1e-12f), 1e12f);
                    if (c0 == lbl[ri]) g_dpos[r] = d0; else minv[ri] = fminf(minv[ri], d0);
                    if (c0 + 1 == lbl[ri]) g_dpos[r] = d1; else minv[ri] = fminf(minv[ri], d1);
                }
            }
#pragma unroll
        for (int ri = 0; ri < 8; ri++) {
            minv[ri] = fminf(minv[ri], __shfl_xor_sync(0xffffffffu, minv[ri], 1));
            minv[ri] = fminf(minv[ri], __shfl_xor_sync(0xffffffffu, minv[ri], 2));
        }
        if (t == 0) {
#pragma unroll
            for (int mt = 0; mt < 4; mt++)
#pragma unroll
                for (int h = 0; h < 2; h++) {
                    int r = mrow0 + warp_m * 64 + mt * 16 + h * 8 + g;
                    atomicMin(&g_rowmin_bits[r], __float_as_uint(minv[mt * 2 + h]));
                }
        }
    } else {
        float* smemT = (float*)smem;       // 128 x LDT floats = 67584 B
        ull rpack[8], cpack[8];
        float colpart[8], rowpart[8];
#pragma unroll
        for (int i = 0; i < 8; i++) {
            rpack[i] = 0xFFFFFFFFFFFFFFFFull;
            cpack[i] = 0xFFFFFFFFFFFFFFFFull;
            colpart[i] = 0.0f; rowpart[i] = 0.0f;
        }
#pragma unroll
        for (int mt = 0; mt < 4; mt++)
#pragma unroll
            for (int h = 0; h < 2; h++) {
                const int ri = mt * 2 + h;
                const int rl = warp_m * 64 + mt * 16 + h * 8 + g;
                const int r = mrow0 + rl;
                const float sa = sarow[ri];
#pragma unroll
                for (int nt = 0; nt < 4; nt++) {
                    const int cl = warp_n * 32 + nt * 8 + t * 2;
                    const int c0 = ncol0 + cl;
                    float d0 = fminf(fmaxf(fmaf(-2.0f, acc[mt][nt][h * 2], sa + sbcol[nt * 2]), 1e-12f), 1e12f);
                    float d1 = fminf(fmaxf(fmaf(-2.0f, acc[mt][nt][h * 2 + 1], sa + sbcol[nt * 2 + 1]), 1e-12f), 1e12f);
                    stcs2(out3 + (size_t)r * CN + c0, d0, d1);
                    smemT[cl * LDT + rl] = d0;
                    smemT[(cl + 1) * LDT + rl] = d1;
                    ull p0 = ((ull)__float_as_uint(d0) << 32) | (unsigned)c0;
                    ull p1 = ((ull)__float_as_uint(d1) << 32) | (unsigned)(c0 + 1);
                    if (c0 != r && p0 < rpack[ri]) rpack[ri] = p0;
                    if (c0 + 1 != r && p1 < rpack[ri]) rpack[ri] = p1;
                    ull q0 = ((ull)__float_as_uint(d0) << 32) | (unsigned)r;
                    ull q1 = ((ull)__float_as_uint(d1) << 32) | (unsigned)r;
                    if (c0 != r && q0 < cpack[nt * 2]) cpack[nt * 2] = q0;
                    if (c0 + 1 != r && q1 < cpack[nt * 2 + 1]) cpack[nt * 2 + 1] = q1;
                    colpart[nt * 2] += d0;
                    colpart[nt * 2 + 1] += d1;
                    rowpart[ri] += d0 + d1;
                }
            }
#pragma unroll
        for (int ri = 0; ri < 8; ri++) {
            rpack[ri] = min(rpack[ri], __shfl_xor_sync(0xffffffffu, rpack[ri], 1));
            rpack[ri] = min(rpack[ri], __shfl_xor_sync(0xffffffffu, rpack[ri], 2));
            rowpart[ri] += __shfl_xor_sync(0xffffffffu, rowpart[ri], 1);
            rowpart[ri] += __shfl_xor_sync(0xffffffffu, rowpart[ri], 2);
        }
        if (t == 0) {
#pragma unroll
            for (int mt = 0; mt < 4; mt++)
#pragma unroll
                for (int h = 0; h < 2; h++) {
                    int r = mrow0 + warp_m * 64 + mt * 16 + h * 8 + g;
                    atomicMin(&g_rowpack[r], rpack[mt * 2 + h]);
                    if (!diag) atomicAdd(&g_colsum[r], rowpart[mt * 2 + h]);
                }
        }
#pragma unroll
        for (int j = 0; j < 8; j++) {
            cpack[j] = min(cpack[j], __shfl_xor_sync(0xffffffffu, cpack[j], 4));
            cpack[j] = min(cpack[j], __shfl_xor_sync(0xffffffffu, cpack[j], 8));
            cpack[j] = min(cpack[j], __shfl_xor_sync(0xffffffffu, cpack[j], 16));
            colpart[j] += __shfl_xor_sync(0xffffffffu, colpart[j], 4);
            colpart[j] += __shfl_xor_sync(0xffffffffu, colpart[j], 8);
            colpart[j] += __shfl_xor_sync(0xffffffffu, colpart[j], 16);
        }
        if (g == 0) {
#pragma unroll
            for (int nt = 0; nt < 4; nt++) {
                int c0 = ncol0 + warp_n * 32 + nt * 8 + t * 2;
                atomicAdd(&g_colsum[c0], colpart[nt * 2]);
                atomicAdd(&g_colsum[c0 + 1], colpart[nt * 2 + 1]);
                if (!diag) {
                    atomicMin(&g_rowpack[c0], cpack[nt * 2]);
                    atomicMin(&g_rowpack[c0 + 1], cpack[nt * 2 + 1]);
                }
            }
        }
        __syncthreads();
        if (!diag) {
            const int cl = tid >> 1;
            const int rh = tid & 1;
            const float* srcrow = &smemT[cl * LDT + rh * 64];
            float* dst = out3 + (size_t)(ncol0 + cl) * CN + mrow0 + rh * 64;
#pragma unroll
            for (int i = 0; i < 32; i++)
                stcs2(dst + i * 2, srcrow[i * 2], srcrow[i * 2 + 1]);
        }
    }
#undef ISSUE_PAIR
}

// ---------------- fused GEMM launch -------------------------------------------
__global__ void __launch_bounds__(256, 2) distmat_all(
    const void* __restrict__ labels, float* __restrict__ out3)
{
    extern __shared__ __align__(16) char smem[];
    int bid = blockIdx.x;
    if (bid < NTRI) {
        int bx = (int)((sqrtf(8.0f * (float)bid + 1.0f) - 1.0f) * 0.5f);
        while ((bx + 1) * (bx + 2) / 2 <= bid) bx++;
        while (bx * (bx + 1) / 2 > bid) bx--;
        int by = bid - bx * (bx + 1) / 2;
        gemm_body<2>(nullptr, out3, smem, bx, by);
    } else {
        int lin = bid - NTRI;
        gemm_body<1>(labels, nullptr, smem, lin & 63, lin >> 6);
    }
}

// ---------------- finalize ----------------------------------------------------
__global__ void finalize_kernel(float* __restrict__ out) {
    __shared__ double red[256];
    int tid = threadIdx.x;

    double s = 0.0;
    for (int i = tid; i < BN; i += 256) {
        float dn = __uint_as_float(g_rowmin_bits[i]);
        s += (double)(g_dpos[i] / (dn + 1.0f));
    }
    red[tid] = s; __syncthreads();
    for (int o = 128; o > 0; o >>= 1) {
        if (tid < o) red[tid] += red[tid + o];
        __syncthreads();
    }
    if (tid == 0) out[0] = (float)(red[0] / (double)BN);
    __syncthreads();

    s = 0.0;
    for (int c = tid; c < CN; c += 256) {
        unsigned j = (unsigned)(g_rowpack[c] & 0xFFFFFFFFull);
        s += (double)g_colsum[j];
    }
    red[tid] = s; __syncthreads();
    for (int o = 128; o > 0; o >>= 1) {
        if (tid < o) red[tid] += red[tid + o];
        __syncthreads();
    }
    if (tid == 0) out[1] = (float)(-red[0] / ((double)CN * (double)CN));
}

// ---------------- launch -------------------------------------------------------
extern "C" void kernel_launch(void* const* d_in, const int* in_sizes, int n_in,
                              void* d_out, int out_size) {
    const float* x = (const float*)d_in[0];
    const void* labels = d_in[1];
    const float* centers = (const float*)d_in[2];
    float* out = (float*)d_out;
    float* out3 = out + 2;

    cudaFuncSetAttribute(distmat_all, cudaFuncAttributeMaxDynamicSharedMemorySize, SMEM_BYTES);

    prep_all<<<2080, 256>>>(x, centers, (const unsigned*)labels);
    distmat_all<<<NTRI + (BN / 128) * (CN / 128), 256, SMEM_BYTES>>>(labels, out3);
    finalize_kernel<<<1, 256>>>(out);
}

// round 17
// speedup vs baseline: 1.0659x; 1.0659x over previous
#include <cuda_runtime.h>
#include <cstdint>

#define BN 8192
#define CN 8192
#define DK 256
#define KC 32
#define NCH (DK / KC)             // 8 chunks (4 pairs)
#define LDRB 96                   // smem row stride bytes ([hi 32][lo 32][pad 32])
#define TILE_B (128 * LDRB)       // 12288 B
#define STAGE_B (2 * TILE_B)      // A + B = 24576 B
#define NSTAGE 4
#define LDT 132
#define NTRI 2080
#define SMEM_BYTES (NSTAGE * STAGE_B)   // 98304

typedef unsigned long long ull;

// ---------------- scratch ----------------------------------------------------
__device__ float g_sqx[BN];
__device__ float g_sqc[CN];
__device__ float g_colsum[CN];
__device__ unsigned g_rowmin_bits[BN];
__device__ ull g_rowpack[CN];
__device__ float g_dpos[BN];
__device__ int g_lab32;

// int8 two-level split, chunk-major: [chunk][row][16 words] = [hi 8w][lo 8w]
// byte order within 32B block matches m16n8k32 s8 fragments:
//   byte 8t+u (u<4): k = 4t+u ; byte 8t+4+u: k = 16+4t+u
__device__ unsigned g_xq[NCH * BN * 16];
__device__ unsigned g_cq[NCH * CN * 16];

__device__ __forceinline__ uint32_t s2u(const void* p) {
    uint32_t a;
    asm("{ .reg .u64 t; cvta.to.shared.u64 t, %1; cvt.u32.u64 %0, t; }" : "=r"(a) : "l"(p));
    return a;
}
__device__ __forceinline__ void cp16(uint32_t dst, const void* src) {
    asm volatile("cp.async.cg.shared.global [%0], [%1], 16;" :: "r"(dst), "l"(src));
}
#define LDS64(r0, r1, addr)                                                     \
    asm volatile("ld.shared.v2.b32 {%0,%1}, [%2];" : "=r"(r0), "=r"(r1) : "r"(addr))
#define MMA_S8(d, a, b)                                                         \
    asm volatile(                                                               \
        "mma.sync.aligned.m16n8k32.row.col.s32.s8.s8.s32 "                      \
        "{%0,%1,%2,%3}, {%4,%5,%6,%7}, {%8,%9}, {%0,%1,%2,%3};"                 \
        : "+r"((d)[0]), "+r"((d)[1]), "+r"((d)[2]), "+r"((d)[3])                \
        : "r"((a)[0]), "r"((a)[1]), "r"((a)[2]), "r"((a)[3]),                   \
          "r"((b)[0]), "r"((b)[1]))

__device__ __forceinline__ unsigned pk4(int b0, int b1, int b2, int b3) {
    return (b0 & 255) | ((b1 & 255) << 8) | ((b2 & 255) << 16) | ((b3 & 255) << 24);
}
__device__ __forceinline__ int q8(float v, float sc) {
    int q = __float2int_rn(v * sc);
    return max(-127, min(127, q));
}

// ---------------- fused prep: init + detect + quantize/interleave + sqnorm ----
__global__ void prep_all(const float* __restrict__ x,
                         const float* __restrict__ centers,
                         const unsigned* __restrict__ lw) {
    int bid = blockIdx.x;
    if (bid >= 2048) {
        int i = (bid - 2048) * 256 + threadIdx.x;
        g_colsum[i] = 0.0f;
        g_rowmin_bits[i] = 0x7F7FFFFFu;
        g_rowpack[i] = 0xFFFFFFFFFFFFFFFFull;
        if (i == 0) g_lab32 = 0;
        if (i < BN / 2) {
            if (lw[2 * i + 1] != 0u) g_lab32 = 1;
        }
        return;
    }
    int which = bid >> 10;
    const float* X = which ? centers : x;
    int row = ((bid & 1023) * 256 + (int)threadIdx.x) >> 5;
    int lane = threadIdx.x & 31;
    const float4* p = reinterpret_cast<const float4*>(X + (size_t)row * DK);
    float4 v0 = p[lane * 2], v1 = p[lane * 2 + 1];        // k = 8*lane .. +7
    float v[8] = {v0.x, v0.y, v0.z, v0.w, v1.x, v1.y, v1.z, v1.w};
    float s = 0.0f;
    int hi[8], lo[8];
#pragma unroll
    for (int i = 0; i < 8; i++) {
        s += v[i] * v[i];
        hi[i] = q8(v[i], 16.0f);
        float r = fmaf((float)-hi[i], 0.0625f, v[i]);
        lo[i] = q8(r, 2048.0f);
    }
    int ch = lane >> 2, q = lane & 3;
    int wa = (q & 1) * 4 + (q >> 1);                      // word pair {wa, wa+2}
    unsigned* dst = (which ? g_cq : g_xq) + ((size_t)ch * BN + row) * 16;
    dst[wa]     = pk4(hi[0], hi[1], hi[2], hi[3]);
    dst[wa + 2] = pk4(hi[4], hi[5], hi[6], hi[7]);
    dst[8 + wa]     = pk4(lo[0], lo[1], lo[2], lo[3]);
    dst[8 + wa + 2] = pk4(lo[4], lo[5], lo[6], lo[7]);
#pragma unroll
    for (int o = 16; o; o >>= 1) s += __shfl_xor_sync(0xffffffffu, s, o);
    if (lane == 0) { if (which) g_sqc[row] = s; else g_sqx[row] = s; }
}

// ---------------- GEMM body: 512 threads, warps 4m x 4n, warp tile 32x32 ------
// dot = D1*2^-8 + D2*2^-15 ; D1 = hi*hi, D2 = hi*lo + lo*hi (int32, exact)
template <int MODE>
__device__ __forceinline__ void gemm_body(
    const void* __restrict__ labels, float* __restrict__ out3,
    char* smem, int bx, int by)
{
    const uint32_t sm0 = s2u(smem);
    const int tid = threadIdx.x;
    const int wid = tid >> 5;
    const int lane = tid & 31;
    const int g = lane >> 2;
    const int t = lane & 3;
    const int warp_m = wid >> 2;   // 0..3
    const int warp_n = wid & 3;    // 0..3
    const int mrow0 = by * 128;
    const int ncol0 = bx * 128;
    const bool diag = (MODE == 2) && (bx == by);

    const char* pA = (const char*)(MODE == 1 ? g_xq : g_cq);
    const char* pB = (const char*)g_cq;
    const int r_ld = tid >> 2;            // 0..127
    const int q_ld = tid & 3;
    const uint32_t dstO = r_ld * LDRB + q_ld * 16;

#define ISSUE_PAIR(pp)                                                         \
    {                                                                          \
        _Pragma("unroll")                                                      \
        for (int cc2 = 0; cc2 < 2; cc2++) {                                    \
            const int c_ = (pp) * 2 + cc2;                                     \
            const uint32_t sb_ = sm0 + (c_ & (NSTAGE - 1)) * STAGE_B;          \
            const size_t ga = ((size_t)(c_ * BN + mrow0 + r_ld)) * 64 + q_ld * 16; \
            const size_t gb = ((size_t)(c_ * CN + ncol0 + r_ld)) * 64 + q_ld * 16; \
            cp16(sb_ + dstO, pA + ga);                                         \
            cp16(sb_ + TILE_B + dstO, pB + gb);                                \
        }                                                                      \
        asm volatile("cp.async.commit_group;");                                \
    }

    int acc1[2][4][4], acc2[2][4][4];
#pragma unroll
    for (int i = 0; i < 2; i++)
#pragma unroll
        for (int j = 0; j < 4; j++)
#pragma unroll
            for (int u = 0; u < 4; u++) { acc1[i][j][u] = 0; acc2[i][j][u] = 0; }

    ISSUE_PAIR(0);

    const uint32_t aAddr0 = (warp_m * 32 + g) * LDRB + t * 8;
    const uint32_t bAddr0 = TILE_B + (warp_n * 32 + g) * LDRB + t * 8;

    for (int p = 0; p < NCH / 2; p++) {
        asm volatile("cp.async.wait_group 0;");
        __syncthreads();
        if (p + 1 < NCH / 2) ISSUE_PAIR(p + 1);

#pragma unroll
        for (int cc = 0; cc < 2; cc++) {
            const int c = 2 * p + cc;
            const uint32_t sb = sm0 + (c & (NSTAGE - 1)) * STAGE_B;
            uint32_t ah[2][4], al[2][4], bh[4][2], bl[4][2];
#pragma unroll
            for (int mt = 0; mt < 2; mt++) {
                uint32_t base = sb + aAddr0 + mt * (16 * LDRB);
                LDS64(ah[mt][0], ah[mt][2], base);
                LDS64(ah[mt][1], ah[mt][3], base + 8 * LDRB);
                LDS64(al[mt][0], al[mt][2], base + 32);
                LDS64(al[mt][1], al[mt][3], base + 8 * LDRB + 32);
            }
#pragma unroll
            for (int nt = 0; nt < 4; nt++) {
                uint32_t bb = sb + bAddr0 + nt * (8 * LDRB);
                LDS64(bh[nt][0], bh[nt][1], bb);
                LDS64(bl[nt][0], bl[nt][1], bb + 32);
            }
#pragma unroll
            for (int mt = 0; mt < 2; mt++)
#pragma unroll
                for (int nt = 0; nt < 4; nt++)
                    MMA_S8(acc1[mt][nt], ah[mt], bh[nt]);
#pragma unroll
            for (int mt = 0; mt < 2; mt++)
#pragma unroll
                for (int nt = 0; nt < 4; nt++) {
                    MMA_S8(acc2[mt][nt], ah[mt], bl[nt]);
                    MMA_S8(acc2[mt][nt], al[mt], bh[nt]);
                }
        }
    }
    __syncthreads();   // pipeline smem free for reuse

#define DOTV(mt, nt, u)                                                        \
    fmaf(__int2float_rn(acc1[mt][nt][u]), 3.90625e-3f,                         \
         __int2float_rn(acc2[mt][nt][u]) * 3.0517578125e-5f)

    // ---------------- epilogue (R14 geometry) ----------------
    const float* sqa = (MODE == 1) ? (const float*)g_sqx : (const float*)g_sqc;
    float sarow[4];
    int lbl[4];
#pragma unroll
    for (int mt = 0; mt < 2; mt++)
#pragma unroll
        for (int h = 0; h < 2; h++) {
            int r = mrow0 + warp_m * 32 + mt * 16 + h * 8 + g;
            sarow[mt * 2 + h] = sqa[r];
            if (MODE == 1)
                lbl[mt * 2 + h] = g_lab32 ? ((const int*)labels)[r]
                                          : (int)((const long long*)labels)[r];
        }
    float sbcol[8];
#pragma unroll
    for (int nt = 0; nt < 4; nt++) {
        int c0 = ncol0 + warp_n * 32 + nt * 8 + t * 2;
        sbcol[nt * 2] = g_sqc[c0];
        sbcol[nt * 2 + 1] = g_sqc[c0 + 1];
    }

    if (MODE == 1) {
        float minv[4];
#pragma unroll
        for (int i = 0; i < 4; i++) minv[i] = 3.0e38f;
#pragma unroll
        for (int mt = 0; mt < 2; mt++)
#pragma unroll
            for (int h = 0; h < 2; h++) {
                const int ri = mt * 2 + h;
                const int r = mrow0 + warp_m * 32 + mt * 16 + h * 8 + g;
                const float sa = sarow[ri];
#pragma unroll
                for (int nt = 0; nt < 4; nt++) {
                    const int c0 = ncol0 + warp_n * 32 + nt * 8 + t * 2;
                    float d0 = fminf(fmaxf(fmaf(-2.0f, DOTV(mt, nt, h * 2), sa + sbcol[nt * 2]), 1e-12f), 1e12f);
                    float d1 = fminf(fmaxf(fmaf(-2.0f, DOTV(mt, nt, h * 2 + 1), sa + sbcol[nt * 2 + 1]), 1e-12f), 1e12f);
                    if (c0 == lbl[ri]) g_dpos[r] = d0; else minv[ri] = fminf(minv[ri], d0);
                    if (c0 + 1 == lbl[ri]) g_dpos[r] = d1; else minv[ri] = fminf(minv[ri], d1);
                }
            }
#pragma unroll
        for (int ri = 0; ri < 4; ri++) {
            minv[ri] = fminf(minv[ri], __shfl_xor_sync(0xffffffffu, minv[ri], 1));
            minv[ri] = fminf(minv[ri], __shfl_xor_sync(0xffffffffu, minv[ri], 2));
        }
        if (t == 0) {
#pragma unroll
            for (int mt = 0; mt < 2; mt++)
#pragma unroll
                for (int h = 0; h < 2; h++) {
                    int r = mrow0 + warp_m * 32 + mt * 16 + h * 8 + g;
                    atomicMin(&g_rowmin_bits[r], __float_as_uint(minv[mt * 2 + h]));
                }
        }
    } else {
        float* smemT = (float*)smem;       // 128 x LDT floats = 67584 B
        ull rpack[4], cpack[8];
        float colpart[8], rowpart[4];
#pragma unroll
        for (int i = 0; i < 4; i++) { rpack[i] = 0xFFFFFFFFFFFFFFFFull; rowpart[i] = 0.0f; }
#pragma unroll
        for (int i = 0; i < 8; i++) { cpack[i] = 0xFFFFFFFFFFFFFFFFull; colpart[i] = 0.0f; }
#pragma unroll
        for (int mt = 0; mt < 2; mt++)
#pragma unroll
            for (int h = 0; h < 2; h++) {
                const int ri = mt * 2 + h;
                const int rl = warp_m * 32 + mt * 16 + h * 8 + g;
                const int r = mrow0 + rl;
                const float sa = sarow[ri];
#pragma unroll
                for (int nt = 0; nt < 4; nt++) {
                    const int cl = warp_n * 32 + nt * 8 + t * 2;
                    const int c0 = ncol0 + cl;
                    float d0 = fminf(fmaxf(fmaf(-2.0f, DOTV(mt, nt, h * 2), sa + sbcol[nt * 2]), 1e-12f), 1e12f);
                    float d1 = fminf(fmaxf(fmaf(-2.0f, DOTV(mt, nt, h * 2 + 1), sa + sbcol[nt * 2 + 1]), 1e-12f), 1e12f);
                    *(float2*)(out3 + (size_t)r * CN + c0) = make_float2(d0, d1);
                    smemT[cl * LDT + rl] = d0;
                    smemT[(cl + 1) * LDT + rl] = d1;
                    ull p0 = ((ull)__float_as_uint(d0) << 32) | (unsigned)c0;
                    ull p1 = ((ull)__float_as_uint(d1) << 32) | (unsigned)(c0 + 1);
                    if (c0 != r && p0 < rpack[ri]) rpack[ri] = p0;
                    if (c0 + 1 != r && p1 < rpack[ri]) rpack[ri] = p1;
                    ull q0 = ((ull)__float_as_uint(d0) << 32) | (unsigned)r;
                    ull q1 = ((ull)__float_as_uint(d1) << 32) | (unsigned)r;
                    if (c0 != r && q0 < cpack[nt * 2]) cpack[nt * 2] = q0;
                    if (c0 + 1 != r && q1 < cpack[nt * 2 + 1]) cpack[nt * 2 + 1] = q1;
                    colpart[nt * 2] += d0;
                    colpart[nt * 2 + 1] += d1;
                    rowpart[ri] += d0 + d1;
                }
            }
#pragma unroll
        for (int ri = 0; ri < 4; ri++) {
            rpack[ri] = min(rpack[ri], __shfl_xor_sync(0xffffffffu, rpack[ri], 1));
            rpack[ri] = min(rpack[ri], __shfl_xor_sync(0xffffffffu, rpack[ri], 2));
            rowpart[ri] += __shfl_xor_sync(0xffffffffu, rowpart[ri], 1);
            rowpart[ri] += __shfl_xor_sync(0xffffffffu, rowpart[ri], 2);
        }
        if (t == 0) {
#pragma unroll
            for (int mt = 0; mt < 2; mt++)
#pragma unroll
                for (int h = 0; h < 2; h++) {
                    int r = mrow0 + warp_m * 32 + mt * 16 + h * 8 + g;
                    atomicMin(&g_rowpack[r], rpack[mt * 2 + h]);
                    if (!diag) atomicAdd(&g_colsum[r], rowpart[mt * 2 + h]);
                }
        }
#pragma unroll
        for (int j = 0; j < 8; j++) {
            cpack[j] = min(cpack[j], __shfl_xor_sync(0xffffffffu, cpack[j], 4));
            cpack[j] = min(cpack[j], __shfl_xor_sync(0xffffffffu, cpack[j], 8));
            cpack[j] = min(cpack[j], __shfl_xor_sync(0xffffffffu, cpack[j], 16));
            colpart[j] += __shfl_xor_sync(0xffffffffu, colpart[j], 4);
            colpart[j] += __shfl_xor_sync(0xffffffffu, colpart[j], 8);
            colpart[j] += __shfl_xor_sync(0xffffffffu, colpart[j], 16);
        }
        if (g == 0) {
#pragma unroll
            for (int nt = 0; nt < 4; nt++) {
                int c0 = ncol0 + warp_n * 32 + nt * 8 + t * 2;
                atomicAdd(&g_colsum[c0], colpart[nt * 2]);
                atomicAdd(&g_colsum[c0 + 1], colpart[nt * 2 + 1]);
                if (!diag) {
                    atomicMin(&g_rowpack[c0], cpack[nt * 2]);
                    atomicMin(&g_rowpack[c0 + 1], cpack[nt * 2 + 1]);
                }
            }
        }
        __syncthreads();
        if (!diag) {
            const int cl = tid >> 2;           // 0..127
            const int rh = tid & 3;            // quarter-rows of 32
            const float* srcrow = &smemT[cl * LDT + rh * 32];
            float* dst = out3 + (size_t)(ncol0 + cl) * CN + mrow0 + rh * 32;
#pragma unroll
            for (int i = 0; i < 16; i++)
                *(float2*)(dst + i * 2) = *(const float2*)(srcrow + i * 2);
        }
    }
#undef ISSUE_PAIR
#undef DOTV
}

// ---------------- fused GEMM launch -------------------------------------------
__global__ void __launch_bounds__(512, 1) distmat_all(
    const void* __restrict__ labels, float* __restrict__ out3)
{
    extern __shared__ __align__(16) char smem[];
    int bid = blockIdx.x;
    if (bid < NTRI) {
        int bx = (int)((sqrtf(8.0f * (float)bid + 1.0f) - 1.0f) * 0.5f);
        while ((bx + 1) * (bx + 2) / 2 <= bid) bx++;
        while (bx * (bx + 1) / 2 > bid) bx--;
        int by = bid - bx * (bx + 1) / 2;
        gemm_body<2>(nullptr, out3, smem, bx, by);
    } else {
        int lin = bid - NTRI;
        gemm_body<1>(labels, nullptr, smem, lin & 63, lin >> 6);
    }
}

// ---------------- finalize ----------------------------------------------------
__global__ void finalize_kernel(float* __restrict__ out) {
    __shared__ double red[256];
    int tid = threadIdx.x;

    double s = 0.0;
    for (int i = tid; i < BN; i += 256) {
        float dn = __uint_as_float(g_rowmin_bits[i]);
        s += (double)(g_dpos[i] / (dn + 1.0f));
    }
    red[tid] = s; __syncthreads();
    for (int o = 128; o > 0; o >>= 1) {
        if (tid < o) red[tid] += red[tid + o];
        __syncthreads();
    }
    if (tid == 0) out[0] = (float)(red[0] / (double)BN);
    __syncthreads();

    s = 0.0;
    for (int c = tid; c < CN; c += 256) {
        unsigned j = (unsigned)(g_rowpack[c] & 0xFFFFFFFFull);
        s += (double)g_colsum[j];
    }
    red[tid] = s; __syncthreads();
    for (int o = 128; o > 0; o >>= 1) {
        if (tid < o) red[tid] += red[tid + o];
        __syncthreads();
    }
    if (tid == 0) out[1] = (float)(-red[0] / ((double)CN * (double)CN));
}

// ---------------- launch -------------------------------------------------------
extern "C" void kernel_launch(void* const* d_in, const int* in_sizes, int n_in,
                              void* d_out, int out_size) {
    const float* x = (const float*)d_in[0];
    const void* labels = d_in[1];
    const float* centers = (const float*)d_in[2];
    float* out = (float*)d_out;
    float* out3 = out + 2;

    cudaFuncSetAttribute(distmat_all, cudaFuncAttributeMaxDynamicSharedMemorySize, SMEM_BYTES);

    prep_all<<<2080, 256>>>(x, centers, (const unsigned*)labels);
    distmat_all<<<NTRI + (BN / 128) * (CN / 128), 512, SMEM_BYTES>>>(labels, out3);
    finalize_kernel<<<1, 256>>>(out);
}